// round 1
// baseline (speedup 1.0000x reference)
#include <cuda_runtime.h>
#include <math.h>

// Problem constants
#define B_    8
#define T_    2048
#define R_    (B_*T_)     // 16384 rows
#define VDIM_ 1024
#define ADIM_ 768
#define DM_   256
#define HID_  1024
#define XDIM_ 768         // 3*DM
#define NBLK_ 4           // HID / 256 column blocks for gate GEMM

// Scratch (allocation-free rule: __device__ globals)
__device__ float g_v[R_*DM_];      // LN(video@Wv+bv)
__device__ float g_rv[R_];         // 1/max(||v_row||, eps)
__device__ float g_a[R_*DM_];      // LN(audio@Wa+ba)
__device__ float g_actx[R_*DM_];   // windowed shifted audio context
__device__ float g_X[R_*XDIM_];    // [an, vn, an*vn]
__device__ float g_plog[R_*NBLK_]; // partial logits per column block

// ---------------------------------------------------------------------------
// K1/K2: projection GEMM (rows x KDIM) @ (KDIM x 256) + bias, fused LayerNorm
// Tile: 64 rows x 256 cols (full width -> LN in-block), BK=16, 256 threads,
// 8x8 per thread. Each warp owns 8 complete rows -> LN stats via shuffles.
// DST: 0 -> write g_v + g_rv, 1 -> write g_a.
// ---------------------------------------------------------------------------
template<int KDIM, int DST>
__global__ __launch_bounds__(256) void proj_ln_kernel(
    const float* __restrict__ A, const float* __restrict__ W,
    const float* __restrict__ bias)
{
    __shared__ float As[16][65];    // padded: conflict-free transposed store
    __shared__ float Bs[16][256];

    const int tid  = threadIdx.x;
    const int lane = tid & 31;
    const int warp = tid >> 5;
    const int row0 = blockIdx.x * 64;

    float c[8][8];
#pragma unroll
    for (int i = 0; i < 8; i++)
#pragma unroll
        for (int j = 0; j < 8; j++) c[i][j] = 0.f;

    const int lm = tid >> 2;          // 0..63 (A-tile row)
    const int lk = (tid & 3) << 2;    // 0,4,8,12 (A-tile k)

    for (int k0 = 0; k0 < KDIM; k0 += 16) {
        // A tile: 64x16, one float4 per thread, store transposed
        float4 av = *(const float4*)(A + (size_t)(row0 + lm) * KDIM + k0 + lk);
        As[lk + 0][lm] = av.x; As[lk + 1][lm] = av.y;
        As[lk + 2][lm] = av.z; As[lk + 3][lm] = av.w;
        // B tile: 16x256, four float4 per thread
#pragma unroll
        for (int i = 0; i < 4; i++) {
            int idx4 = tid + (i << 8);        // 0..1023
            int bk = idx4 >> 6;               // 0..15
            int bn = (idx4 & 63) << 2;        // 0..252
            *(float4*)&Bs[bk][bn] =
                *(const float4*)(W + (size_t)(k0 + bk) * DM_ + bn);
        }
        __syncthreads();
#pragma unroll
        for (int kk = 0; kk < 16; kk++) {
            float af[8];
#pragma unroll
            for (int i = 0; i < 8; i++) af[i] = As[kk][(warp << 3) + i];
            float4 bA = *(const float4*)&Bs[kk][lane << 3];
            float4 bB = *(const float4*)&Bs[kk][(lane << 3) + 4];
            float bf[8] = {bA.x, bA.y, bA.z, bA.w, bB.x, bB.y, bB.z, bB.w};
#pragma unroll
            for (int i = 0; i < 8; i++)
#pragma unroll
                for (int j = 0; j < 8; j++)
                    c[i][j] = fmaf(af[i], bf[j], c[i][j]);
        }
        __syncthreads();
    }

    // bias
    float bj[8];
#pragma unroll
    for (int j = 0; j < 8; j++) bj[j] = bias[(lane << 3) + j];
#pragma unroll
    for (int i = 0; i < 8; i++)
#pragma unroll
        for (int j = 0; j < 8; j++) c[i][j] += bj[j];

    float* outV = (DST == 0) ? g_v : g_a;

    // Per-row LayerNorm (warp owns rows warp*8+i entirely)
#pragma unroll
    for (int i = 0; i < 8; i++) {
        float s = 0.f, ss = 0.f;
#pragma unroll
        for (int j = 0; j < 8; j++) {
            s += c[i][j];
            ss = fmaf(c[i][j], c[i][j], ss);
        }
#pragma unroll
        for (int off = 16; off > 0; off >>= 1) {
            s  += __shfl_xor_sync(0xffffffffu, s,  off);
            ss += __shfl_xor_sync(0xffffffffu, ss, off);
        }
        float mu   = s * (1.f / 256.f);
        float var  = fmaxf(ss * (1.f / 256.f) - mu * mu, 0.f);
        float rstd = rsqrtf(var + 1e-5f);
        int grow = row0 + (warp << 3) + i;
        float vrow[8];
#pragma unroll
        for (int j = 0; j < 8; j++) vrow[j] = (c[i][j] - mu) * rstd;
        float4 o0 = {vrow[0], vrow[1], vrow[2], vrow[3]};
        float4 o1 = {vrow[4], vrow[5], vrow[6], vrow[7]};
        *(float4*)(outV + (size_t)grow * DM_ + (lane << 3))     = o0;
        *(float4*)(outV + (size_t)grow * DM_ + (lane << 3) + 4) = o1;
        if (DST == 0 && lane == 0) {
            // ||v|| = sqrt(256*var)/sqrt(var+eps)
            float l2 = sqrtf(256.f * var) * rstd;
            g_rv[grow] = 1.f / fmaxf(l2, 1e-8f);
        }
    }
}

// ---------------------------------------------------------------------------
// K3: temporal shift (scalar delta) + causal window average + build X rows.
// One block per (b,t) row, 256 threads = one feature each.
// center = min(t+delta, t) = t since delta in (2,6); window tau in [t-5, t].
// ---------------------------------------------------------------------------
__global__ __launch_bounds__(256) void ctx_kernel(const float* __restrict__ theta)
{
    __shared__ float red[8];
    const int row = blockIdx.x;
    const int d   = threadIdx.x;
    const int b   = row >> 11;      // /2048
    const int t   = row & 2047;

    float th    = fminf(fmaxf(theta[0], -12.f), 12.f);
    float delta = 2.f + 4.f / (1.f + expf(-th));
    float nf    = floorf(delta);
    float alpha = delta - nf;
    int   ni    = (int)nf;

    const int lo = max(0, t - 5);
    const float inv_cnt = 1.f / (float)(t - lo + 1);

    const float* ab = g_a + ((size_t)b * T_) * DM_;
    float acc = 0.f;
    for (int tau = lo; tau <= t; tau++) {
        int i0 = min(max(tau - ni, 0), T_ - 1);
        int i1 = min(i0 + 1, T_ - 1);
        acc += (1.f - alpha) * ab[(size_t)i0 * DM_ + d]
             +        alpha  * ab[(size_t)i1 * DM_ + d];
    }
    float ac = acc * inv_cnt;

    // block-reduce sum of squares for l2 norm of a_ctx row
    float ss = ac * ac;
#pragma unroll
    for (int off = 16; off > 0; off >>= 1)
        ss += __shfl_xor_sync(0xffffffffu, ss, off);
    int lane = d & 31, warp = d >> 5;
    if (lane == 0) red[warp] = ss;
    __syncthreads();
    if (d == 0) {
        float tot = 0.f;
#pragma unroll
        for (int k = 0; k < 8; k++) tot += red[k];
        red[0] = tot;
    }
    __syncthreads();
    float norm = sqrtf(red[0]);
    float ra   = 1.f / fmaxf(norm, 1e-8f);

    float vn = g_v[(size_t)row * DM_ + d] * g_rv[row];
    float an = ac * ra;

    g_actx[(size_t)row * DM_ + d] = ac;
    float* xr = g_X + (size_t)row * XDIM_;
    xr[d]           = an;
    xr[DM_ + d]     = vn;
    xr[2 * DM_ + d] = an * vn;
}

// ---------------------------------------------------------------------------
// K4: gate MLP. GEMM X[16384x768] @ W1[768x1024] tile 64x256 (BK=16),
// epilogue: + b1, exact gelu, x W2[col], warp-reduce over 256 cols ->
// partial logit per (row, column-block). Deterministic (fixed shuffle tree).
// ---------------------------------------------------------------------------
__global__ __launch_bounds__(256) void mlp_kernel(
    const float* __restrict__ W1, const float* __restrict__ b1,
    const float* __restrict__ W2)
{
    __shared__ float As[16][65];
    __shared__ float Bs[16][256];

    const int tid  = threadIdx.x;
    const int lane = tid & 31;
    const int warp = tid >> 5;
    const int row0 = blockIdx.x * 64;
    const int gn0  = blockIdx.y * 256;

    float c[8][8];
#pragma unroll
    for (int i = 0; i < 8; i++)
#pragma unroll
        for (int j = 0; j < 8; j++) c[i][j] = 0.f;

    const int lm = tid >> 2;
    const int lk = (tid & 3) << 2;

    for (int k0 = 0; k0 < XDIM_; k0 += 16) {
        float4 av = *(const float4*)(g_X + (size_t)(row0 + lm) * XDIM_ + k0 + lk);
        As[lk + 0][lm] = av.x; As[lk + 1][lm] = av.y;
        As[lk + 2][lm] = av.z; As[lk + 3][lm] = av.w;
#pragma unroll
        for (int i = 0; i < 4; i++) {
            int idx4 = tid + (i << 8);
            int bk = idx4 >> 6;
            int bn = (idx4 & 63) << 2;
            *(float4*)&Bs[bk][bn] =
                *(const float4*)(W1 + (size_t)(k0 + bk) * HID_ + gn0 + bn);
        }
        __syncthreads();
#pragma unroll
        for (int kk = 0; kk < 16; kk++) {
            float af[8];
#pragma unroll
            for (int i = 0; i < 8; i++) af[i] = As[kk][(warp << 3) + i];
            float4 bA = *(const float4*)&Bs[kk][lane << 3];
            float4 bB = *(const float4*)&Bs[kk][(lane << 3) + 4];
            float bf[8] = {bA.x, bA.y, bA.z, bA.w, bB.x, bB.y, bB.z, bB.w};
#pragma unroll
            for (int i = 0; i < 8; i++)
#pragma unroll
                for (int j = 0; j < 8; j++)
                    c[i][j] = fmaf(af[i], bf[j], c[i][j]);
        }
        __syncthreads();
    }

    const int coln = gn0 + (lane << 3);
    float b1f[8], w2f[8];
#pragma unroll
    for (int j = 0; j < 8; j++) { b1f[j] = b1[coln + j]; w2f[j] = W2[coln + j]; }

    float pl[8];
#pragma unroll
    for (int i = 0; i < 8; i++) pl[i] = 0.f;
#pragma unroll
    for (int i = 0; i < 8; i++)
#pragma unroll
        for (int j = 0; j < 8; j++) {
            float x = c[i][j] + b1f[j];
            float h = 0.5f * x * (1.f + erff(x * 0.7071067811865476f)); // exact gelu
            pl[i] = fmaf(h, w2f[j], pl[i]);
        }
#pragma unroll
    for (int i = 0; i < 8; i++) {
#pragma unroll
        for (int off = 16; off > 0; off >>= 1)
            pl[i] += __shfl_xor_sync(0xffffffffu, pl[i], off);
        if (lane == 0)
            g_plog[(size_t)(row0 + (warp << 3) + i) * NBLK_ + blockIdx.y] = pl[i];
    }
}

// ---------------------------------------------------------------------------
// K5: finish logit, gate, mix. One block per row.
// ---------------------------------------------------------------------------
__global__ __launch_bounds__(256) void out_kernel(
    const float* __restrict__ b2, float* __restrict__ out)
{
    const int row = blockIdx.x;
    const int d   = threadIdx.x;
    float s = b2[0];
#pragma unroll
    for (int k = 0; k < NBLK_; k++) s += g_plog[(size_t)row * NBLK_ + k];
    s = fminf(fmaxf(s, -12.f), 12.f);
    float g = 1.f / (1.f + expf(-s));
    g = fminf(fmaxf(g, 0.05f), 0.95f);
    float ac = g_actx[(size_t)row * DM_ + d];
    float vv = g_v[(size_t)row * DM_ + d];
    out[(size_t)row * DM_ + d] = g * ac + (1.f - g) * vv;
}

// ---------------------------------------------------------------------------
extern "C" void kernel_launch(void* const* d_in, const int* in_sizes, int n_in,
                              void* d_out, int out_size)
{
    const float* video = (const float*)d_in[0];
    const float* audio = (const float*)d_in[1];
    const float* Wv    = (const float*)d_in[2];
    const float* bv    = (const float*)d_in[3];
    const float* Wa    = (const float*)d_in[4];
    const float* ba    = (const float*)d_in[5];
    const float* theta = (const float*)d_in[6];
    const float* W1    = (const float*)d_in[7];
    const float* b1    = (const float*)d_in[8];
    const float* W2    = (const float*)d_in[9];
    const float* b2    = (const float*)d_in[10];
    float* out = (float*)d_out;

    proj_ln_kernel<VDIM_, 0><<<R_ / 64, 256>>>(video, Wv, bv);
    proj_ln_kernel<ADIM_, 1><<<R_ / 64, 256>>>(audio, Wa, ba);
    ctx_kernel<<<R_, 256>>>(theta);
    mlp_kernel<<<dim3(R_ / 64, NBLK_), 256>>>(W1, b1, W2);
    out_kernel<<<R_, 256>>>(b2, out);
}

// round 2
// speedup vs baseline: 1.4914x; 1.4914x over previous
#include <cuda_runtime.h>
#include <mma.h>
#include <math.h>

using namespace nvcuda;

// Problem constants
#define B_    8
#define T_    2048
#define R_    (B_*T_)     // 16384 rows
#define VDIM_ 1024
#define ADIM_ 768
#define DM_   256
#define HID_  1024
#define XDIM_ 768         // 3*DM
#define NBLK_ 8           // HID / 128 column blocks for gate GEMM

// Scratch (allocation-free rule: __device__ globals)
__device__ float g_v[R_*DM_];      // raw video proj -> LN'd in place
__device__ float g_rv[R_];         // 1/max(||v_row||, eps)
__device__ float g_a[R_*DM_];      // raw audio proj -> LN'd in place
__device__ float g_actx[R_*DM_];   // windowed shifted audio context
__device__ float g_X[R_*XDIM_];    // [an, vn, an*vn]
__device__ float g_plog[R_*NBLK_]; // partial logits per 128-col block

__device__ __forceinline__ float to_tf32(float x) {
    float r;
    asm("cvt.rna.tf32.f32 %0, %1;" : "=f"(r) : "f"(x));
    return r;
}

// ---------------------------------------------------------------------------
// Generic TF32 tensor-core GEMM: C[R x NOUT] = A[R x KDIM] @ W[KDIM x NOUT]
// Tile 128x128, BK=32, 256 threads = 8 warps (4x2), warp tile 32x64,
// wmma 16x16x8 tf32 fragments. Raw output (bias handled downstream).
// ---------------------------------------------------------------------------
#define ALD 36     // A smem leading dim (128 x 36)
#define BLD 132    // B smem leading dim (32 x 132)
#define A_SZ (128*ALD)

template<int KDIM, int NOUT>
__global__ __launch_bounds__(256) void gemm_tf32_kernel(
    const float* __restrict__ A, const float* __restrict__ W,
    float* __restrict__ C)
{
    extern __shared__ float sh[];
    float* As = sh;            // 128 x 36
    float* Bs = sh + A_SZ;     // 32 x 132

    const int tid  = threadIdx.x;
    const int lane = tid & 31;
    const int warp = tid >> 5;
    const int wr   = warp >> 1;     // 0..3
    const int wc   = warp & 1;      // 0..1
    const int row0 = blockIdx.x * 128;
    const int n0   = blockIdx.y * 128;

    wmma::fragment<wmma::accumulator, 16, 16, 8, float> acc[2][4];
#pragma unroll
    for (int i = 0; i < 2; i++)
#pragma unroll
        for (int j = 0; j < 4; j++) wmma::fill_fragment(acc[i][j], 0.f);

    for (int k0 = 0; k0 < KDIM; k0 += 32) {
        // Stage A tile 128x32 (1024 float4s over 256 threads)
#pragma unroll
        for (int i = 0; i < 4; i++) {
            int f4 = tid + (i << 8);
            int r  = f4 >> 3;
            int c  = (f4 & 7) << 2;
            float4 v = *(const float4*)(A + (size_t)(row0 + r) * KDIM + k0 + c);
            As[r * ALD + c + 0] = to_tf32(v.x);
            As[r * ALD + c + 1] = to_tf32(v.y);
            As[r * ALD + c + 2] = to_tf32(v.z);
            As[r * ALD + c + 3] = to_tf32(v.w);
        }
        // Stage B tile 32x128
#pragma unroll
        for (int i = 0; i < 4; i++) {
            int f4 = tid + (i << 8);
            int r  = f4 >> 5;
            int c  = (f4 & 31) << 2;
            float4 v = *(const float4*)(W + (size_t)(k0 + r) * NOUT + n0 + c);
            Bs[r * BLD + c + 0] = to_tf32(v.x);
            Bs[r * BLD + c + 1] = to_tf32(v.y);
            Bs[r * BLD + c + 2] = to_tf32(v.z);
            Bs[r * BLD + c + 3] = to_tf32(v.w);
        }
        __syncthreads();

#pragma unroll
        for (int kk = 0; kk < 32; kk += 8) {
            wmma::fragment<wmma::matrix_a, 16, 16, 8, wmma::precision::tf32,
                           wmma::row_major> af[2];
            wmma::fragment<wmma::matrix_b, 16, 16, 8, wmma::precision::tf32,
                           wmma::row_major> bf[4];
#pragma unroll
            for (int i = 0; i < 2; i++)
                wmma::load_matrix_sync(af[i],
                    As + (wr * 32 + i * 16) * ALD + kk, ALD);
#pragma unroll
            for (int j = 0; j < 4; j++)
                wmma::load_matrix_sync(bf[j],
                    Bs + kk * BLD + wc * 64 + j * 16, BLD);
#pragma unroll
            for (int i = 0; i < 2; i++)
#pragma unroll
                for (int j = 0; j < 4; j++)
                    wmma::mma_sync(acc[i][j], af[i], bf[j], acc[i][j]);
        }
        __syncthreads();
    }

#pragma unroll
    for (int i = 0; i < 2; i++)
#pragma unroll
        for (int j = 0; j < 4; j++)
            wmma::store_matrix_sync(
                C + (size_t)(row0 + wr * 32 + i * 16) * NOUT
                  + n0 + wc * 64 + j * 16,
                acc[i][j], NOUT, wmma::mem_row_major);
}

// ---------------------------------------------------------------------------
// LN pass: adds bias, LayerNorms in place. y=0 -> g_v (+ g_rv), y=1 -> g_a.
// One block per row, 256 threads.
// ---------------------------------------------------------------------------
__global__ __launch_bounds__(256) void ln_kernel(
    const float* __restrict__ bv, const float* __restrict__ ba)
{
    __shared__ float redS[8], redQ[8], bc[2];
    const int row = blockIdx.x;
    const int d   = threadIdx.x;
    float* buf = blockIdx.y ? g_a : g_v;
    const float* bias = blockIdx.y ? ba : bv;

    float x = buf[(size_t)row * DM_ + d] + bias[d];
    float s = x, q = x * x;
#pragma unroll
    for (int off = 16; off > 0; off >>= 1) {
        s += __shfl_xor_sync(0xffffffffu, s, off);
        q += __shfl_xor_sync(0xffffffffu, q, off);
    }
    int lane = d & 31, warp = d >> 5;
    if (lane == 0) { redS[warp] = s; redQ[warp] = q; }
    __syncthreads();
    if (d == 0) {
        float ts = 0.f, tq = 0.f;
#pragma unroll
        for (int k = 0; k < 8; k++) { ts += redS[k]; tq += redQ[k]; }
        float mu  = ts * (1.f / 256.f);
        float var = fmaxf(tq * (1.f / 256.f) - mu * mu, 0.f);
        bc[0] = mu;
        bc[1] = rsqrtf(var + 1e-5f);
        if (blockIdx.y == 0) {
            float l2 = sqrtf(256.f * var) * bc[1];
            g_rv[row] = 1.f / fmaxf(l2, 1e-8f);
        }
    }
    __syncthreads();
    buf[(size_t)row * DM_ + d] = (x - bc[0]) * bc[1];
}

// ---------------------------------------------------------------------------
// ctx: temporal shift + causal 6-tap window average + build X rows.
// center = min(t+delta, t) = t since delta in (2,6); window tau in [t-5, t].
// ---------------------------------------------------------------------------
__global__ __launch_bounds__(256) void ctx_kernel(const float* __restrict__ theta)
{
    __shared__ float red[8];
    const int row = blockIdx.x;
    const int d   = threadIdx.x;
    const int b   = row >> 11;
    const int t   = row & 2047;

    float th    = fminf(fmaxf(theta[0], -12.f), 12.f);
    float delta = 2.f + 4.f / (1.f + expf(-th));
    float nf    = floorf(delta);
    float alpha = delta - nf;
    int   ni    = (int)nf;

    const int lo = max(0, t - 5);
    const float inv_cnt = 1.f / (float)(t - lo + 1);

    const float* ab = g_a + ((size_t)b * T_) * DM_;
    float acc = 0.f;
    for (int tau = lo; tau <= t; tau++) {
        int i0 = min(max(tau - ni, 0), T_ - 1);
        int i1 = min(i0 + 1, T_ - 1);
        acc += (1.f - alpha) * ab[(size_t)i0 * DM_ + d]
             +        alpha  * ab[(size_t)i1 * DM_ + d];
    }
    float ac = acc * inv_cnt;

    float ss = ac * ac;
#pragma unroll
    for (int off = 16; off > 0; off >>= 1)
        ss += __shfl_xor_sync(0xffffffffu, ss, off);
    int lane = d & 31, warp = d >> 5;
    if (lane == 0) red[warp] = ss;
    __syncthreads();
    if (d == 0) {
        float tot = 0.f;
#pragma unroll
        for (int k = 0; k < 8; k++) tot += red[k];
        red[0] = tot;
    }
    __syncthreads();
    float ra = 1.f / fmaxf(sqrtf(red[0]), 1e-8f);

    float vn = g_v[(size_t)row * DM_ + d] * g_rv[row];
    float an = ac * ra;

    g_actx[(size_t)row * DM_ + d] = ac;
    float* xr = g_X + (size_t)row * XDIM_;
    xr[d]           = an;
    xr[DM_ + d]     = vn;
    xr[2 * DM_ + d] = an * vn;
}

// ---------------------------------------------------------------------------
// mlp: TF32 GEMM X[16384x768] @ W1[768x1024], tile 128x128; epilogue stages C
// in smem, then +b1, exact gelu, x W2, warp-reduce -> partial logit per
// (row, 128-col block). Deterministic fixed shuffle tree.
// ---------------------------------------------------------------------------
#define CLD 132
__global__ __launch_bounds__(256) void mlp_kernel(
    const float* __restrict__ W1, const float* __restrict__ b1,
    const float* __restrict__ W2)
{
    extern __shared__ float sh[];
    float* As = sh;
    float* Bs = sh + A_SZ;

    const int tid  = threadIdx.x;
    const int lane = tid & 31;
    const int warp = tid >> 5;
    const int wr   = warp >> 1;
    const int wc   = warp & 1;
    const int row0 = blockIdx.x * 128;
    const int n0   = blockIdx.y * 128;

    wmma::fragment<wmma::accumulator, 16, 16, 8, float> acc[2][4];
#pragma unroll
    for (int i = 0; i < 2; i++)
#pragma unroll
        for (int j = 0; j < 4; j++) wmma::fill_fragment(acc[i][j], 0.f);

    for (int k0 = 0; k0 < XDIM_; k0 += 32) {
#pragma unroll
        for (int i = 0; i < 4; i++) {
            int f4 = tid + (i << 8);
            int r  = f4 >> 3;
            int c  = (f4 & 7) << 2;
            float4 v = *(const float4*)(g_X + (size_t)(row0 + r) * XDIM_ + k0 + c);
            As[r * ALD + c + 0] = to_tf32(v.x);
            As[r * ALD + c + 1] = to_tf32(v.y);
            As[r * ALD + c + 2] = to_tf32(v.z);
            As[r * ALD + c + 3] = to_tf32(v.w);
        }
#pragma unroll
        for (int i = 0; i < 4; i++) {
            int f4 = tid + (i << 8);
            int r  = f4 >> 5;
            int c  = (f4 & 31) << 2;
            float4 v = *(const float4*)(W1 + (size_t)(k0 + r) * HID_ + n0 + c);
            Bs[r * BLD + c + 0] = to_tf32(v.x);
            Bs[r * BLD + c + 1] = to_tf32(v.y);
            Bs[r * BLD + c + 2] = to_tf32(v.z);
            Bs[r * BLD + c + 3] = to_tf32(v.w);
        }
        __syncthreads();
#pragma unroll
        for (int kk = 0; kk < 32; kk += 8) {
            wmma::fragment<wmma::matrix_a, 16, 16, 8, wmma::precision::tf32,
                           wmma::row_major> af[2];
            wmma::fragment<wmma::matrix_b, 16, 16, 8, wmma::precision::tf32,
                           wmma::row_major> bf[4];
#pragma unroll
            for (int i = 0; i < 2; i++)
                wmma::load_matrix_sync(af[i],
                    As + (wr * 32 + i * 16) * ALD + kk, ALD);
#pragma unroll
            for (int j = 0; j < 4; j++)
                wmma::load_matrix_sync(bf[j],
                    Bs + kk * BLD + wc * 64 + j * 16, BLD);
#pragma unroll
            for (int i = 0; i < 2; i++)
#pragma unroll
                for (int j = 0; j < 4; j++)
                    wmma::mma_sync(acc[i][j], af[i], bf[j], acc[i][j]);
        }
        __syncthreads();
    }

    // Stage C tile into smem (reuses As/Bs space; all reads done)
    float* Cs = sh;   // 128 x 132
#pragma unroll
    for (int i = 0; i < 2; i++)
#pragma unroll
        for (int j = 0; j < 4; j++)
            wmma::store_matrix_sync(
                Cs + (wr * 32 + i * 16) * CLD + wc * 64 + j * 16,
                acc[i][j], CLD, wmma::mem_row_major);
    __syncthreads();

    // Epilogue: each warp owns 16 rows; lane covers cols lane, +32, +64, +96
    float b1f[4], w2f[4];
#pragma unroll
    for (int q = 0; q < 4; q++) {
        int gcol = n0 + lane + q * 32;
        b1f[q] = b1[gcol];
        w2f[q] = W2[gcol];
    }
#pragma unroll
    for (int rr = 0; rr < 16; rr++) {
        int r = warp * 16 + rr;
        float p = 0.f;
#pragma unroll
        for (int q = 0; q < 4; q++) {
            float x = Cs[r * CLD + lane + q * 32] + b1f[q];
            float h = 0.5f * x * (1.f + erff(x * 0.7071067811865476f));
            p = fmaf(h, w2f[q], p);
        }
#pragma unroll
        for (int off = 16; off > 0; off >>= 1)
            p += __shfl_xor_sync(0xffffffffu, p, off);
        if (lane == 0)
            g_plog[(size_t)(row0 + r) * NBLK_ + blockIdx.y] = p;
    }
}

// ---------------------------------------------------------------------------
// out: finish logit, gate, mix. One block per row.
// ---------------------------------------------------------------------------
__global__ __launch_bounds__(256) void out_kernel(
    const float* __restrict__ b2, float* __restrict__ out)
{
    const int row = blockIdx.x;
    const int d   = threadIdx.x;
    float s = b2[0];
#pragma unroll
    for (int k = 0; k < NBLK_; k++) s += g_plog[(size_t)row * NBLK_ + k];
    s = fminf(fmaxf(s, -12.f), 12.f);
    float g = 1.f / (1.f + expf(-s));
    g = fminf(fmaxf(g, 0.05f), 0.95f);
    float ac = g_actx[(size_t)row * DM_ + d];
    float vv = g_v[(size_t)row * DM_ + d];
    out[(size_t)row * DM_ + d] = g * ac + (1.f - g) * vv;
}

// ---------------------------------------------------------------------------
extern "C" void kernel_launch(void* const* d_in, const int* in_sizes, int n_in,
                              void* d_out, int out_size)
{
    const float* video = (const float*)d_in[0];
    const float* audio = (const float*)d_in[1];
    const float* Wv    = (const float*)d_in[2];
    const float* bv    = (const float*)d_in[3];
    const float* Wa    = (const float*)d_in[4];
    const float* ba    = (const float*)d_in[5];
    const float* theta = (const float*)d_in[6];
    const float* W1    = (const float*)d_in[7];
    const float* b1    = (const float*)d_in[8];
    const float* W2    = (const float*)d_in[9];
    const float* b2    = (const float*)d_in[10];
    float* out = (float*)d_out;

    const int gemm_smem = (A_SZ + 32 * BLD) * sizeof(float);   // 35328 B
    const int mlp_smem  = 128 * CLD * sizeof(float);           // 67584 B
    cudaFuncSetAttribute(mlp_kernel,
        cudaFuncAttributeMaxDynamicSharedMemorySize, mlp_smem);

    float* gv;  cudaGetSymbolAddress((void**)&gv, g_v);
    float* ga;  cudaGetSymbolAddress((void**)&ga, g_a);

    gemm_tf32_kernel<VDIM_, DM_><<<dim3(R_/128, DM_/128), 256, gemm_smem>>>(
        video, Wv, gv);
    gemm_tf32_kernel<ADIM_, DM_><<<dim3(R_/128, DM_/128), 256, gemm_smem>>>(
        audio, Wa, ga);
    ln_kernel<<<dim3(R_, 2), 256>>>(bv, ba);
    ctx_kernel<<<R_, 256>>>(theta);
    mlp_kernel<<<dim3(R_/128, HID_/128), 256, mlp_smem>>>(W1, b1, W2);
    out_kernel<<<R_, 256>>>(b2, out);
}